// round 11
// baseline (speedup 1.0000x reference)
#include <cuda_runtime.h>
#include <math.h>

#define NN 100000
#define NE 1000000
#define D  64

#define SCAN_T 1024
#define NBLK ((NN + SCAN_T - 1) / SCAN_T)   // 98

// ---------------- scratch (device globals; no allocation allowed) ----------------
__device__ float g_H[NN * D];       // per-layer GEMM output (gather source)
__device__ float g_OUT[NN * D];     // reduce output / next-layer input
__device__ int   g_degS[NN];
__device__ int   g_degR[NN];
__device__ float g_invSs[NN];       // rsqrt(degS + 1)  (with self edges)
__device__ float g_invRs[NN];       // rsqrt(degR + 1)
__device__ float g_invS0[NN];       // rsqrt(max(degS,1)) (no self edges)
__device__ float g_invR0[NN];       // rsqrt(max(degR,1))
__device__ int   g_idx64;           // 1 if edge indices are int64
// CSR-by-receiver build (per replay)
__device__ int   g_incl[NN];        // per-block inclusive scan of degR
__device__ int   g_blockSums[NBLK];
__device__ int   g_blockOff[NBLK];  // exclusive scan of block sums
__device__ int   g_rowStart[NN + 1];
__device__ int   g_cursor[NN];
__device__ int   g_srcIdx[NE];      // sender ids grouped by receiver

// ---------------- index dtype detection ----------------
__global__ void detect_idx_kernel(const int* __restrict__ s) {
    if (blockIdx.x == 0 && threadIdx.x == 0) {
        int ok = 1;
        for (int i = 0; i < 1024; i++) {
            if (s[2 * i + 1] != 0) { ok = 0; break; }
        }
        g_idx64 = ok;
    }
}

__device__ __forceinline__ int edge_id(const void* p, int e, int is64) {
    if (is64) return (int)((const long long*)p)[e];
    return ((const int*)p)[e];
}

// ---------------- degree computation ----------------
__global__ void zero_deg_kernel() {
    int i = blockIdx.x * blockDim.x + threadIdx.x;
    if (i < NN) { g_degS[i] = 0; g_degR[i] = 0; }
}

__global__ void count_deg_kernel(const void* __restrict__ S, const void* __restrict__ R) {
    int e = blockIdx.x * blockDim.x + threadIdx.x;
    if (e >= NE) return;
    int is64 = g_idx64;
    atomicAdd(&g_degS[edge_id(S, e, is64)], 1);
    atomicAdd(&g_degR[edge_id(R, e, is64)], 1);
}

// ---------------- CSR build: 2-level scan + bin fill ----------------
__global__ void scan1_kernel() {
    __shared__ int sm[SCAN_T];
    int b = blockIdx.x, t = threadIdx.x;
    int i = b * SCAN_T + t;
    int v = (i < NN) ? g_degR[i] : 0;
    sm[t] = v;
    __syncthreads();
#pragma unroll
    for (int off = 1; off < SCAN_T; off <<= 1) {
        int add = (t >= off) ? sm[t - off] : 0;
        __syncthreads();
        sm[t] += add;
        __syncthreads();
    }
    if (i < NN) g_incl[i] = sm[t];
    if (t == SCAN_T - 1) g_blockSums[b] = sm[t];
}

__global__ void scan2_kernel() {
    if (threadIdx.x == 0) {
        int acc = 0;
        for (int b = 0; b < NBLK; b++) {
            g_blockOff[b] = acc;
            acc += g_blockSums[b];
        }
    }
}

// exclusive row starts, cursor init, and inverse-sqrt degree scales
__global__ void scan3_kernel() {
    int i = blockIdx.x * blockDim.x + threadIdx.x;
    if (i < NN) {
        int excl = g_incl[i] - g_degR[i] + g_blockOff[i / SCAN_T];
        g_rowStart[i] = excl;
        g_cursor[i]   = excl;
        float ds = (float)g_degS[i];
        float dr = (float)g_degR[i];
        g_invSs[i] = rsqrtf(ds + 1.0f);
        g_invRs[i] = rsqrtf(dr + 1.0f);
        g_invS0[i] = rsqrtf(fmaxf(ds, 1.0f));
        g_invR0[i] = rsqrtf(fmaxf(dr, 1.0f));
    }
    if (i == 0) g_rowStart[NN] = NE;
}

__global__ void fill_kernel(const void* __restrict__ S, const void* __restrict__ R) {
    int e = blockIdx.x * blockDim.x + threadIdx.x;
    if (e >= NE) return;
    int is64 = g_idx64;
    int s = edge_id(S, e, is64);
    int r = edge_id(R, e, is64);
    int pos = atomicAdd(&g_cursor[r], 1);
    g_srcIdx[pos] = s;
}

// ---------------- fused GEMM + bias + tanh + sender-degree scaling ----------------
// h = tanh?( X[r] @ W + b ) * sOut[r]  -> H only (no accumulator writes)
template <int COLS, bool TANH>
__global__ void gemm_kernel(const float* __restrict__ X,
                            const float* __restrict__ W,
                            const float* __restrict__ bias,
                            const float* __restrict__ sOut,
                            float* __restrict__ H) {
    constexpr int CG = COLS / 4;
    constexpr int THREADS = 16 * CG;
    __shared__ float sW[64 * COLS];
    __shared__ float sX[64 * 68];

    const int tid  = threadIdx.x;
    const int row0 = blockIdx.x * 64;

    for (int i = tid; i < 64 * CG; i += THREADS)
        ((float4*)sW)[i] = ((const float4*)W)[i];

    for (int i = tid; i < 64 * 16; i += THREADS) {
        int r  = i >> 4;
        int kq = i & 15;
        int row = row0 + r;
        float4 v = make_float4(0.f, 0.f, 0.f, 0.f);
        if (row < NN) v = ((const float4*)X)[row * 16 + kq];
        ((float4*)sX)[r * 17 + kq] = v;
    }
    __syncthreads();

    const int cg = tid % CG;
    const int rg = tid / CG;

    float acc[4][4];
#pragma unroll
    for (int i = 0; i < 4; i++)
#pragma unroll
        for (int j = 0; j < 4; j++) acc[i][j] = 0.f;

#pragma unroll 16
    for (int k = 0; k < 64; k++) {
        float4 wv = ((const float4*)sW)[k * CG + cg];
#pragma unroll
        for (int i = 0; i < 4; i++) {
            float xv = sX[(rg * 4 + i) * 68 + k];
            acc[i][0] = fmaf(xv, wv.x, acc[i][0]);
            acc[i][1] = fmaf(xv, wv.y, acc[i][1]);
            acc[i][2] = fmaf(xv, wv.z, acc[i][2]);
            acc[i][3] = fmaf(xv, wv.w, acc[i][3]);
        }
    }

    float4 bv = ((const float4*)bias)[cg];
#pragma unroll
    for (int i = 0; i < 4; i++) {
        int row = row0 + rg * 4 + i;
        if (row < NN) {
            float4 o;
            o.x = acc[i][0] + bv.x;
            o.y = acc[i][1] + bv.y;
            o.z = acc[i][2] + bv.z;
            o.w = acc[i][3] + bv.w;
            if (TANH) {
                o.x = tanhf(o.x); o.y = tanhf(o.y);
                o.z = tanhf(o.z); o.w = tanhf(o.w);
            }
            float so = sOut[row];
            o.x *= so; o.y *= so; o.z *= so; o.w *= so;
            ((float4*)H)[row * CG + cg] = o;
        }
    }
}

// ---------------- gather-reduce per receiver (CSR), 64 cols ----------------
// One warp per receiver; lane owns a float2 column pair.
// OUT[r] = (SELF ? H[r] : 0 + sum_{s in seg(r)} H[s]) * invR[r]
template <bool SELF>
__global__ void reduce64_kernel(const float* __restrict__ H,
                                const float* __restrict__ invR,
                                float* __restrict__ OUT) {
    int warp = (blockIdx.x * blockDim.x + threadIdx.x) >> 5;
    int lane = threadIdx.x & 31;
    if (warp >= NN) return;
    const int r   = warp;
    const int beg = g_rowStart[r];
    const int end = g_rowStart[r + 1];

    float2 acc = make_float2(0.f, 0.f);
    if (SELF) acc = ((const float2*)H)[r * 32 + lane];

    for (int j = beg; j < end; j++) {
        int s = g_srcIdx[j];
        float2 v = __ldg(&((const float2*)H)[s * 32 + lane]);
        acc.x += v.x; acc.y += v.y;
    }
    float sc = invR[r];
    acc.x *= sc; acc.y *= sc;
    ((float2*)OUT)[r * 32 + lane] = acc;
}

// ---------------- gather-reduce, 16 cols: 4 lanes per receiver ----------------
__global__ void reduce16_kernel(const float* __restrict__ H,
                                const float* __restrict__ invR,
                                float* __restrict__ OUT) {
    int gid  = (blockIdx.x * blockDim.x + threadIdx.x) >> 2;   // receiver
    int lane = threadIdx.x & 3;                                // float4 part
    if (gid >= NN) return;
    const int beg = g_rowStart[gid];
    const int end = g_rowStart[gid + 1];

    float4 acc = make_float4(0.f, 0.f, 0.f, 0.f);
    for (int j = beg; j < end; j++) {
        int s = g_srcIdx[j];
        float4 v = __ldg(&((const float4*)H)[s * 4 + lane]);
        acc.x += v.x; acc.y += v.y; acc.z += v.z; acc.w += v.w;
    }
    float sc = invR[gid];
    acc.x *= sc; acc.y *= sc; acc.z *= sc; acc.w *= sc;
    ((float4*)OUT)[gid * 4 + lane] = acc;
}

// ---------------- launch ----------------
extern "C" void kernel_launch(void* const* d_in, const int* in_sizes, int n_in,
                              void* d_out, int out_size) {
    const float* nodes = (const float*)d_in[0];
    const void*  S     = d_in[1];
    const void*  R     = d_in[2];
    const float* W0    = (const float*)d_in[3];
    const float* b0    = (const float*)d_in[4];
    const float* W1    = (const float*)d_in[5];
    const float* b1    = (const float*)d_in[6];
    const float* W2    = (const float*)d_in[7];
    const float* b2    = (const float*)d_in[8];
    float* out = (float*)d_out;

    void *pH, *pO, *pSs, *pRs, *pS0, *pR0;
    cudaGetSymbolAddress(&pH,  g_H);
    cudaGetSymbolAddress(&pO,  g_OUT);
    cudaGetSymbolAddress(&pSs, g_invSs);
    cudaGetSymbolAddress(&pRs, g_invRs);
    cudaGetSymbolAddress(&pS0, g_invS0);
    cudaGetSymbolAddress(&pR0, g_invR0);
    float* H     = (float*)pH;
    float* OUT   = (float*)pO;
    float* invSs = (float*)pSs;
    float* invRs = (float*)pRs;
    float* invS0 = (float*)pS0;
    float* invR0 = (float*)pR0;

    const int nodeBlocks = (NN + 255) / 256;
    const int edgeBlocks = (NE + 255) / 256;
    const int gemmBlocks = (NN + 63) / 64;
    const int red64Blocks = (NN * 32 + 255) / 256;  // warp per receiver
    const int red16Blocks = (NN * 4 + 255) / 256;   // 4 lanes per receiver

    // ---- CSR build (per replay; reused by all 3 layers) ----
    detect_idx_kernel<<<1, 32>>>((const int*)S);
    zero_deg_kernel<<<nodeBlocks, 256>>>();
    count_deg_kernel<<<edgeBlocks, 256>>>(S, R);
    scan1_kernel<<<NBLK, SCAN_T>>>();
    scan2_kernel<<<1, 32>>>();
    scan3_kernel<<<nodeBlocks, 256>>>();
    fill_kernel<<<edgeBlocks, 256>>>(S, R);

    // layer 0: tanh, self edges
    gemm_kernel<64, true><<<gemmBlocks, 256>>>(nodes, W0, b0, invSs, H);
    reduce64_kernel<true><<<red64Blocks, 256>>>(H, invRs, OUT);

    // layer 1: tanh, self edges
    gemm_kernel<64, true><<<gemmBlocks, 256>>>(OUT, W1, b1, invSs, H);
    reduce64_kernel<true><<<red64Blocks, 256>>>(H, invRs, OUT);

    // layer 2: linear, no self edges, output straight to d_out
    gemm_kernel<16, false><<<gemmBlocks, 64>>>(OUT, W2, b2, invS0, H);
    reduce16_kernel<<<red16Blocks, 256>>>(H, invR0, out);
}

// round 12
// speedup vs baseline: 1.0309x; 1.0309x over previous
#include <cuda_runtime.h>
#include <math.h>

#define NN 100000
#define NE 1000000
#define D  64

#define SCAN_T 1024
#define NBLK ((NN + SCAN_T - 1) / SCAN_T)   // 98

// ---------------- scratch (device globals; no allocation allowed) ----------------
__device__ float g_H[NN * D];       // per-layer GEMM output (gather source)
__device__ float g_OUT[NN * D];     // reduce output / next-layer input
__device__ int   g_degS[NN];
__device__ int   g_degR[NN];
__device__ float g_invSs[NN];       // rsqrt(degS + 1)  (with self edges)
__device__ float g_invRs[NN];       // rsqrt(degR + 1)
__device__ float g_invS0[NN];       // rsqrt(max(degS,1)) (no self edges)
__device__ float g_invR0[NN];       // rsqrt(max(degR,1))
__device__ int   g_idx64;           // 1 if edge indices are int64
// CSR-by-receiver build (per replay)
__device__ int   g_incl[NN];        // per-block inclusive scan of degR
__device__ int   g_blockSums[NBLK];
__device__ int   g_blockOff[NBLK];  // exclusive scan of block sums
__device__ int   g_rowStart[NN + 1];
__device__ int   g_cursor[NN];
__device__ int   g_srcIdx[NE];      // sender ids grouped by receiver

// ---------------- index dtype detection ----------------
__global__ void detect_idx_kernel(const int* __restrict__ s) {
    if (blockIdx.x == 0 && threadIdx.x == 0) {
        int ok = 1;
        for (int i = 0; i < 1024; i++) {
            if (s[2 * i + 1] != 0) { ok = 0; break; }
        }
        g_idx64 = ok;
    }
}

__device__ __forceinline__ int edge_id(const void* p, int e, int is64) {
    if (is64) return (int)((const long long*)p)[e];
    return ((const int*)p)[e];
}

// ---------------- degree computation ----------------
__global__ void zero_deg_kernel() {
    int i = blockIdx.x * blockDim.x + threadIdx.x;
    if (i < NN) { g_degS[i] = 0; g_degR[i] = 0; }
}

__global__ void count_deg_kernel(const void* __restrict__ S, const void* __restrict__ R) {
    int e = blockIdx.x * blockDim.x + threadIdx.x;
    if (e >= NE) return;
    int is64 = g_idx64;
    atomicAdd(&g_degS[edge_id(S, e, is64)], 1);
    atomicAdd(&g_degR[edge_id(R, e, is64)], 1);
}

// ---------------- CSR build: 2-level scan + bin fill ----------------
__global__ void scan1_kernel() {
    __shared__ int sm[SCAN_T];
    int b = blockIdx.x, t = threadIdx.x;
    int i = b * SCAN_T + t;
    int v = (i < NN) ? g_degR[i] : 0;
    sm[t] = v;
    __syncthreads();
#pragma unroll
    for (int off = 1; off < SCAN_T; off <<= 1) {
        int add = (t >= off) ? sm[t - off] : 0;
        __syncthreads();
        sm[t] += add;
        __syncthreads();
    }
    if (i < NN) g_incl[i] = sm[t];
    if (t == SCAN_T - 1) g_blockSums[b] = sm[t];
}

__global__ void scan2_kernel() {
    if (threadIdx.x == 0) {
        int acc = 0;
        for (int b = 0; b < NBLK; b++) {
            g_blockOff[b] = acc;
            acc += g_blockSums[b];
        }
    }
}

// exclusive row starts, cursor init, and inverse-sqrt degree scales
__global__ void scan3_kernel() {
    int i = blockIdx.x * blockDim.x + threadIdx.x;
    if (i < NN) {
        int excl = g_incl[i] - g_degR[i] + g_blockOff[i / SCAN_T];
        g_rowStart[i] = excl;
        g_cursor[i]   = excl;
        float ds = (float)g_degS[i];
        float dr = (float)g_degR[i];
        g_invSs[i] = rsqrtf(ds + 1.0f);
        g_invRs[i] = rsqrtf(dr + 1.0f);
        g_invS0[i] = rsqrtf(fmaxf(ds, 1.0f));
        g_invR0[i] = rsqrtf(fmaxf(dr, 1.0f));
    }
    if (i == 0) g_rowStart[NN] = NE;
}

__global__ void fill_kernel(const void* __restrict__ S, const void* __restrict__ R) {
    int e = blockIdx.x * blockDim.x + threadIdx.x;
    if (e >= NE) return;
    int is64 = g_idx64;
    int s = edge_id(S, e, is64);
    int r = edge_id(R, e, is64);
    int pos = atomicAdd(&g_cursor[r], 1);
    g_srcIdx[pos] = s;
}

// ---------------- fused GEMM + bias + tanh + sender-degree scaling ----------------
// h = tanh?( X[r] @ W + b ) * sOut[r]  -> H only (no accumulator writes)
template <int COLS, bool TANH>
__global__ void gemm_kernel(const float* __restrict__ X,
                            const float* __restrict__ W,
                            const float* __restrict__ bias,
                            const float* __restrict__ sOut,
                            float* __restrict__ H) {
    constexpr int CG = COLS / 4;
    constexpr int THREADS = 16 * CG;
    __shared__ float sW[64 * COLS];
    __shared__ float sX[64 * 68];

    const int tid  = threadIdx.x;
    const int row0 = blockIdx.x * 64;

    for (int i = tid; i < 64 * CG; i += THREADS)
        ((float4*)sW)[i] = ((const float4*)W)[i];

    for (int i = tid; i < 64 * 16; i += THREADS) {
        int r  = i >> 4;
        int kq = i & 15;
        int row = row0 + r;
        float4 v = make_float4(0.f, 0.f, 0.f, 0.f);
        if (row < NN) v = ((const float4*)X)[row * 16 + kq];
        ((float4*)sX)[r * 17 + kq] = v;
    }
    __syncthreads();

    const int cg = tid % CG;
    const int rg = tid / CG;

    float acc[4][4];
#pragma unroll
    for (int i = 0; i < 4; i++)
#pragma unroll
        for (int j = 0; j < 4; j++) acc[i][j] = 0.f;

#pragma unroll 16
    for (int k = 0; k < 64; k++) {
        float4 wv = ((const float4*)sW)[k * CG + cg];
#pragma unroll
        for (int i = 0; i < 4; i++) {
            float xv = sX[(rg * 4 + i) * 68 + k];
            acc[i][0] = fmaf(xv, wv.x, acc[i][0]);
            acc[i][1] = fmaf(xv, wv.y, acc[i][1]);
            acc[i][2] = fmaf(xv, wv.z, acc[i][2]);
            acc[i][3] = fmaf(xv, wv.w, acc[i][3]);
        }
    }

    float4 bv = ((const float4*)bias)[cg];
#pragma unroll
    for (int i = 0; i < 4; i++) {
        int row = row0 + rg * 4 + i;
        if (row < NN) {
            float4 o;
            o.x = acc[i][0] + bv.x;
            o.y = acc[i][1] + bv.y;
            o.z = acc[i][2] + bv.z;
            o.w = acc[i][3] + bv.w;
            if (TANH) {
                o.x = tanhf(o.x); o.y = tanhf(o.y);
                o.z = tanhf(o.z); o.w = tanhf(o.w);
            }
            float so = sOut[row];
            o.x *= so; o.y *= so; o.z *= so; o.w *= so;
            ((float4*)H)[row * CG + cg] = o;
        }
    }
}

// ---------------- gather-reduce per receiver (CSR), 64 cols ----------------
// One warp per receiver; lane owns a float2 column pair.
// OUT[r] = (SELF ? H[r] : 0 + sum_{s in seg(r)} H[s]) * invR[r]
template <bool SELF>
__global__ void reduce64_kernel(const float* __restrict__ H,
                                const float* __restrict__ invR,
                                float* __restrict__ OUT) {
    int warp = (blockIdx.x * blockDim.x + threadIdx.x) >> 5;
    int lane = threadIdx.x & 31;
    if (warp >= NN) return;
    const int r   = warp;
    const int beg = g_rowStart[r];
    const int end = g_rowStart[r + 1];

    float2 acc = make_float2(0.f, 0.f);
    if (SELF) acc = ((const float2*)H)[r * 32 + lane];

    for (int j = beg; j < end; j++) {
        int s = g_srcIdx[j];
        float2 v = __ldg(&((const float2*)H)[s * 32 + lane]);
        acc.x += v.x; acc.y += v.y;
    }
    float sc = invR[r];
    acc.x *= sc; acc.y *= sc;
    ((float2*)OUT)[r * 32 + lane] = acc;
}

// ---------------- gather-reduce, 16 cols: 4 lanes per receiver ----------------
__global__ void reduce16_kernel(const float* __restrict__ H,
                                const float* __restrict__ invR,
                                float* __restrict__ OUT) {
    int gid  = (blockIdx.x * blockDim.x + threadIdx.x) >> 2;   // receiver
    int lane = threadIdx.x & 3;                                // float4 part
    if (gid >= NN) return;
    const int beg = g_rowStart[gid];
    const int end = g_rowStart[gid + 1];

    float4 acc = make_float4(0.f, 0.f, 0.f, 0.f);
    for (int j = beg; j < end; j++) {
        int s = g_srcIdx[j];
        float4 v = __ldg(&((const float4*)H)[s * 4 + lane]);
        acc.x += v.x; acc.y += v.y; acc.z += v.z; acc.w += v.w;
    }
    float sc = invR[gid];
    acc.x *= sc; acc.y *= sc; acc.z *= sc; acc.w *= sc;
    ((float4*)OUT)[gid * 4 + lane] = acc;
}

// ---------------- launch ----------------
extern "C" void kernel_launch(void* const* d_in, const int* in_sizes, int n_in,
                              void* d_out, int out_size) {
    const float* nodes = (const float*)d_in[0];
    const void*  S     = d_in[1];
    const void*  R     = d_in[2];
    const float* W0    = (const float*)d_in[3];
    const float* b0    = (const float*)d_in[4];
    const float* W1    = (const float*)d_in[5];
    const float* b1    = (const float*)d_in[6];
    const float* W2    = (const float*)d_in[7];
    const float* b2    = (const float*)d_in[8];
    float* out = (float*)d_out;

    void *pH, *pO, *pSs, *pRs, *pS0, *pR0;
    cudaGetSymbolAddress(&pH,  g_H);
    cudaGetSymbolAddress(&pO,  g_OUT);
    cudaGetSymbolAddress(&pSs, g_invSs);
    cudaGetSymbolAddress(&pRs, g_invRs);
    cudaGetSymbolAddress(&pS0, g_invS0);
    cudaGetSymbolAddress(&pR0, g_invR0);
    float* H     = (float*)pH;
    float* OUT   = (float*)pO;
    float* invSs = (float*)pSs;
    float* invRs = (float*)pRs;
    float* invS0 = (float*)pS0;
    float* invR0 = (float*)pR0;

    const int nodeBlocks = (NN + 255) / 256;
    const int edgeBlocks = (NE + 255) / 256;
    const int gemmBlocks = (NN + 63) / 64;
    const int red64Blocks = (NN * 32 + 255) / 256;  // warp per receiver
    const int red16Blocks = (NN * 4 + 255) / 256;   // 4 lanes per receiver

    // ---- CSR build (per replay; reused by all 3 layers) ----
    detect_idx_kernel<<<1, 32>>>((const int*)S);
    zero_deg_kernel<<<nodeBlocks, 256>>>();
    count_deg_kernel<<<edgeBlocks, 256>>>(S, R);
    scan1_kernel<<<NBLK, SCAN_T>>>();
    scan2_kernel<<<1, 32>>>();
    scan3_kernel<<<nodeBlocks, 256>>>();
    fill_kernel<<<edgeBlocks, 256>>>(S, R);

    // layer 0: tanh, self edges
    gemm_kernel<64, true><<<gemmBlocks, 256>>>(nodes, W0, b0, invSs, H);
    reduce64_kernel<true><<<red64Blocks, 256>>>(H, invRs, OUT);

    // layer 1: tanh, self edges
    gemm_kernel<64, true><<<gemmBlocks, 256>>>(OUT, W1, b1, invSs, H);
    reduce64_kernel<true><<<red64Blocks, 256>>>(H, invRs, OUT);

    // layer 2: linear, no self edges, output straight to d_out
    gemm_kernel<16, false><<<gemmBlocks, 64>>>(OUT, W2, b2, invS0, H);
    reduce16_kernel<<<red16Blocks, 256>>>(H, invR0, out);
}

// round 13
// speedup vs baseline: 1.0414x; 1.0101x over previous
#include <cuda_runtime.h>
#include <math.h>

#define NN 100000
#define NE 1000000
#define D  64

#define SCAN_T 1024
#define NBLK ((NN + SCAN_T - 1) / SCAN_T)   // 98

// ---------------- scratch (device globals; no allocation allowed) ----------------
__device__ float g_H[NN * D];       // per-layer GEMM output (gather source)
__device__ float g_OUT[NN * D];     // reduce output / next-layer input
__device__ int   g_degS[NN];
__device__ int   g_degR[NN];
__device__ float g_invSs[NN];       // rsqrt(degS + 1)  (with self edges)
__device__ float g_invRs[NN];       // rsqrt(degR + 1)
__device__ float g_invS0[NN];       // rsqrt(max(degS,1)) (no self edges)
__device__ float g_invR0[NN];       // rsqrt(max(degR,1))
__device__ int   g_idx64;           // 1 if edge indices are int64
// CSR-by-receiver build (per replay)
__device__ int   g_incl[NN];        // per-block inclusive scan of degR
__device__ int   g_blockSums[NBLK];
__device__ int   g_blockOff[NBLK];  // exclusive scan of block sums
__device__ int   g_rowStart[NN + 1];
__device__ int   g_cursor[NN];
__device__ int   g_srcIdx[NE];      // sender ids grouped by receiver

// ---------------- index dtype detection ----------------
__global__ void detect_idx_kernel(const int* __restrict__ s) {
    if (blockIdx.x == 0 && threadIdx.x == 0) {
        int ok = 1;
        for (int i = 0; i < 1024; i++) {
            if (s[2 * i + 1] != 0) { ok = 0; break; }
        }
        g_idx64 = ok;
    }
}

__device__ __forceinline__ int edge_id(const void* p, int e, int is64) {
    if (is64) return (int)((const long long*)p)[e];
    return ((const int*)p)[e];
}

// ---------------- degree computation ----------------
__global__ void zero_deg_kernel() {
    int i = blockIdx.x * blockDim.x + threadIdx.x;
    if (i < NN) { g_degS[i] = 0; g_degR[i] = 0; }
}

__global__ void count_deg_kernel(const void* __restrict__ S, const void* __restrict__ R) {
    int e = blockIdx.x * blockDim.x + threadIdx.x;
    if (e >= NE) return;
    int is64 = g_idx64;
    atomicAdd(&g_degS[edge_id(S, e, is64)], 1);
    atomicAdd(&g_degR[edge_id(R, e, is64)], 1);
}

// ---------------- CSR build: 2-level scan + bin fill ----------------
__global__ void scan1_kernel() {
    __shared__ int sm[SCAN_T];
    int b = blockIdx.x, t = threadIdx.x;
    int i = b * SCAN_T + t;
    int v = (i < NN) ? g_degR[i] : 0;
    sm[t] = v;
    __syncthreads();
#pragma unroll
    for (int off = 1; off < SCAN_T; off <<= 1) {
        int add = (t >= off) ? sm[t - off] : 0;
        __syncthreads();
        sm[t] += add;
        __syncthreads();
    }
    if (i < NN) g_incl[i] = sm[t];
    if (t == SCAN_T - 1) g_blockSums[b] = sm[t];
}

__global__ void scan2_kernel() {
    if (threadIdx.x == 0) {
        int acc = 0;
        for (int b = 0; b < NBLK; b++) {
            g_blockOff[b] = acc;
            acc += g_blockSums[b];
        }
    }
}

// exclusive row starts, cursor init, and inverse-sqrt degree scales
__global__ void scan3_kernel() {
    int i = blockIdx.x * blockDim.x + threadIdx.x;
    if (i < NN) {
        int excl = g_incl[i] - g_degR[i] + g_blockOff[i / SCAN_T];
        g_rowStart[i] = excl;
        g_cursor[i]   = excl;
        float ds = (float)g_degS[i];
        float dr = (float)g_degR[i];
        g_invSs[i] = rsqrtf(ds + 1.0f);
        g_invRs[i] = rsqrtf(dr + 1.0f);
        g_invS0[i] = rsqrtf(fmaxf(ds, 1.0f));
        g_invR0[i] = rsqrtf(fmaxf(dr, 1.0f));
    }
    if (i == 0) g_rowStart[NN] = NE;
}

__global__ void fill_kernel(const void* __restrict__ S, const void* __restrict__ R) {
    int e = blockIdx.x * blockDim.x + threadIdx.x;
    if (e >= NE) return;
    int is64 = g_idx64;
    int s = edge_id(S, e, is64);
    int r = edge_id(R, e, is64);
    int pos = atomicAdd(&g_cursor[r], 1);
    g_srcIdx[pos] = s;
}

// ---------------- fused GEMM + bias + tanh + sender-degree scaling ----------------
// h = tanh?( X[r] @ W + b ) * sOut[r]  -> H only (no accumulator writes)
template <int COLS, bool TANH>
__global__ void gemm_kernel(const float* __restrict__ X,
                            const float* __restrict__ W,
                            const float* __restrict__ bias,
                            const float* __restrict__ sOut,
                            float* __restrict__ H) {
    constexpr int CG = COLS / 4;
    constexpr int THREADS = 16 * CG;
    __shared__ float sW[64 * COLS];
    __shared__ float sX[64 * 68];

    const int tid  = threadIdx.x;
    const int row0 = blockIdx.x * 64;

    for (int i = tid; i < 64 * CG; i += THREADS)
        ((float4*)sW)[i] = ((const float4*)W)[i];

    for (int i = tid; i < 64 * 16; i += THREADS) {
        int r  = i >> 4;
        int kq = i & 15;
        int row = row0 + r;
        float4 v = make_float4(0.f, 0.f, 0.f, 0.f);
        if (row < NN) v = ((const float4*)X)[row * 16 + kq];
        ((float4*)sX)[r * 17 + kq] = v;
    }
    __syncthreads();

    const int cg = tid % CG;
    const int rg = tid / CG;

    float acc[4][4];
#pragma unroll
    for (int i = 0; i < 4; i++)
#pragma unroll
        for (int j = 0; j < 4; j++) acc[i][j] = 0.f;

#pragma unroll 16
    for (int k = 0; k < 64; k++) {
        float4 wv = ((const float4*)sW)[k * CG + cg];
#pragma unroll
        for (int i = 0; i < 4; i++) {
            float xv = sX[(rg * 4 + i) * 68 + k];
            acc[i][0] = fmaf(xv, wv.x, acc[i][0]);
            acc[i][1] = fmaf(xv, wv.y, acc[i][1]);
            acc[i][2] = fmaf(xv, wv.z, acc[i][2]);
            acc[i][3] = fmaf(xv, wv.w, acc[i][3]);
        }
    }

    float4 bv = ((const float4*)bias)[cg];
#pragma unroll
    for (int i = 0; i < 4; i++) {
        int row = row0 + rg * 4 + i;
        if (row < NN) {
            float4 o;
            o.x = acc[i][0] + bv.x;
            o.y = acc[i][1] + bv.y;
            o.z = acc[i][2] + bv.z;
            o.w = acc[i][3] + bv.w;
            if (TANH) {
                o.x = tanhf(o.x); o.y = tanhf(o.y);
                o.z = tanhf(o.z); o.w = tanhf(o.w);
            }
            float so = sOut[row];
            o.x *= so; o.y *= so; o.z *= so; o.w *= so;
            ((float4*)H)[row * CG + cg] = o;
        }
    }
}

// ---------------- gather-reduce per receiver (CSR), 64 cols ----------------
// One warp per receiver; lane owns a float2 column pair.
// OUT[r] = (SELF ? H[r] : 0 + sum_{s in seg(r)} H[s]) * invR[r]
template <bool SELF>
__global__ void reduce64_kernel(const float* __restrict__ H,
                                const float* __restrict__ invR,
                                float* __restrict__ OUT) {
    int warp = (blockIdx.x * blockDim.x + threadIdx.x) >> 5;
    int lane = threadIdx.x & 31;
    if (warp >= NN) return;
    const int r   = warp;
    const int beg = g_rowStart[r];
    const int end = g_rowStart[r + 1];

    float2 acc = make_float2(0.f, 0.f);
    if (SELF) acc = ((const float2*)H)[r * 32 + lane];

    for (int j = beg; j < end; j++) {
        int s = g_srcIdx[j];
        float2 v = __ldg(&((const float2*)H)[s * 32 + lane]);
        acc.x += v.x; acc.y += v.y;
    }
    float sc = invR[r];
    acc.x *= sc; acc.y *= sc;
    ((float2*)OUT)[r * 32 + lane] = acc;
}

// ---------------- gather-reduce, 16 cols: 4 lanes per receiver ----------------
__global__ void reduce16_kernel(const float* __restrict__ H,
                                const float* __restrict__ invR,
                                float* __restrict__ OUT) {
    int gid  = (blockIdx.x * blockDim.x + threadIdx.x) >> 2;   // receiver
    int lane = threadIdx.x & 3;                                // float4 part
    if (gid >= NN) return;
    const int beg = g_rowStart[gid];
    const int end = g_rowStart[gid + 1];

    float4 acc = make_float4(0.f, 0.f, 0.f, 0.f);
    for (int j = beg; j < end; j++) {
        int s = g_srcIdx[j];
        float4 v = __ldg(&((const float4*)H)[s * 4 + lane]);
        acc.x += v.x; acc.y += v.y; acc.z += v.z; acc.w += v.w;
    }
    float sc = invR[gid];
    acc.x *= sc; acc.y *= sc; acc.z *= sc; acc.w *= sc;
    ((float4*)OUT)[gid * 4 + lane] = acc;
}

// ---------------- launch ----------------
extern "C" void kernel_launch(void* const* d_in, const int* in_sizes, int n_in,
                              void* d_out, int out_size) {
    const float* nodes = (const float*)d_in[0];
    const void*  S     = d_in[1];
    const void*  R     = d_in[2];
    const float* W0    = (const float*)d_in[3];
    const float* b0    = (const float*)d_in[4];
    const float* W1    = (const float*)d_in[5];
    const float* b1    = (const float*)d_in[6];
    const float* W2    = (const float*)d_in[7];
    const float* b2    = (const float*)d_in[8];
    float* out = (float*)d_out;

    void *pH, *pO, *pSs, *pRs, *pS0, *pR0;
    cudaGetSymbolAddress(&pH,  g_H);
    cudaGetSymbolAddress(&pO,  g_OUT);
    cudaGetSymbolAddress(&pSs, g_invSs);
    cudaGetSymbolAddress(&pRs, g_invRs);
    cudaGetSymbolAddress(&pS0, g_invS0);
    cudaGetSymbolAddress(&pR0, g_invR0);
    float* H     = (float*)pH;
    float* OUT   = (float*)pO;
    float* invSs = (float*)pSs;
    float* invRs = (float*)pRs;
    float* invS0 = (float*)pS0;
    float* invR0 = (float*)pR0;

    const int nodeBlocks = (NN + 255) / 256;
    const int edgeBlocks = (NE + 255) / 256;
    const int gemmBlocks = (NN + 63) / 64;
    const int red64Blocks = (NN * 32 + 255) / 256;  // warp per receiver
    const int red16Blocks = (NN * 4 + 255) / 256;   // 4 lanes per receiver

    // ---- CSR build (per replay; reused by all 3 layers) ----
    detect_idx_kernel<<<1, 32>>>((const int*)S);
    zero_deg_kernel<<<nodeBlocks, 256>>>();
    count_deg_kernel<<<edgeBlocks, 256>>>(S, R);
    scan1_kernel<<<NBLK, SCAN_T>>>();
    scan2_kernel<<<1, 32>>>();
    scan3_kernel<<<nodeBlocks, 256>>>();
    fill_kernel<<<edgeBlocks, 256>>>(S, R);

    // layer 0: tanh, self edges
    gemm_kernel<64, true><<<gemmBlocks, 256>>>(nodes, W0, b0, invSs, H);
    reduce64_kernel<true><<<red64Blocks, 256>>>(H, invRs, OUT);

    // layer 1: tanh, self edges
    gemm_kernel<64, true><<<gemmBlocks, 256>>>(OUT, W1, b1, invSs, H);
    reduce64_kernel<true><<<red64Blocks, 256>>>(H, invRs, OUT);

    // layer 2: linear, no self edges, output straight to d_out
    gemm_kernel<16, false><<<gemmBlocks, 64>>>(OUT, W2, b2, invS0, H);
    reduce16_kernel<<<red16Blocks, 256>>>(H, invR0, out);
}